// round 11
// baseline (speedup 1.0000x reference)
#include <cuda_runtime.h>
#include <cuda_fp16.h>
#include <stdint.h>

#define NMAX 100000
#define EMAX 1600000
#define D 64

// Scratch (static device globals: allocation-free, graph-capturable).
// g_deg starts zero-initialized and is RESET in the gemm epilogue each
// launch, so graph replays are deterministic.
__device__ __half g_xsh[(size_t)NMAX * D];  // xs = (x@W)*dinv[row], fp16
__device__ float  g_deg[NMAX];
__device__ float  g_dinv[NMAX];

// ---------------------------------------------------------------------------
// K1: deg[dst[e]] += 1 (deg starts 0; self-loop folded into rsqrt later)
// 4 edges per thread via int4; one tail group handles the remainder.
// ---------------------------------------------------------------------------
__global__ void deg_count_kernel(const int* __restrict__ dst, int E)
{
    int g = blockIdx.x * blockDim.x + threadIdx.x;
    int nquad = E >> 2;
    if (g < nquad) {
        int4 dd = *(const int4*)&dst[4 * g];
        atomicAdd(&g_deg[dd.x], 1.0f);
        atomicAdd(&g_deg[dd.y], 1.0f);
        atomicAdd(&g_deg[dd.z], 1.0f);
        atomicAdd(&g_deg[dd.w], 1.0f);
    } else if (g == nquad) {
        for (int e = 4 * nquad; e < E; e++)
            atomicAdd(&g_deg[__ldg(&dst[e])], 1.0f);
    }
}

// ---------------------------------------------------------------------------
// K2: fused projection + normalization epilogue.
//   di        = rsqrt(deg[row]+1)   (computed by lane c4==0, shfl-broadcast)
//   dinv[row] = di;  deg[row] = 0   (reset for graph replay)
//   xsh[row]  = (x@W)[row] * di     (fp16 message row)
//   out[row]  = (x@W)[row]*di*di + b  (self-loop + bias, fp32 path)
// 256 threads, 64 rows/block, 4 rows x 4 cols register blocking.
// k-loop unrolled by 4 with LDS.128 broadcast x-row reads.
// ---------------------------------------------------------------------------
__global__ void __launch_bounds__(256) gemm64_kernel(
    const float* __restrict__ x, const float* __restrict__ W,
    const float* __restrict__ b, float* __restrict__ out, int n)
{
    __shared__ float  sX[64][68];   // 68: keeps 16B alignment of row starts
    __shared__ float4 sW[64][16];

    const int t = threadIdx.x;
    const int rowBase = blockIdx.x * 64;

    {
        const float4* W4 = (const float4*)W;
        #pragma unroll
        for (int i = 0; i < 4; i++) {
            int idx = t + i * 256;
            sW[idx >> 4][idx & 15] = W4[idx];
        }
    }
    {
        #pragma unroll
        for (int i = 0; i < 4; i++) {
            int idx = t + i * 256;
            int r = idx >> 4, c4 = idx & 15;
            int row = rowBase + r;
            float4 v = make_float4(0.f, 0.f, 0.f, 0.f);
            if (row < n) v = ((const float4*)(x + (size_t)row * D))[c4];
            *(float4*)&sX[r][c4 * 4] = v;
        }
    }
    __syncthreads();

    const int c4 = t & 15;
    const int r0 = t >> 4;

    float4 acc[4];
    #pragma unroll
    for (int r = 0; r < 4; r++) acc[r] = make_float4(0.f, 0.f, 0.f, 0.f);

    #pragma unroll
    for (int k = 0; k < 64; k += 4) {
        float4 w0 = sW[k + 0][c4];
        float4 w1 = sW[k + 1][c4];
        float4 w2 = sW[k + 2][c4];
        float4 w3 = sW[k + 3][c4];
        #pragma unroll
        for (int r = 0; r < 4; r++) {
            float4 xv = *(const float4*)&sX[r0 + 16 * r][k];  // LDS.128 broadcast
            acc[r].x += xv.x * w0.x + xv.y * w1.x + xv.z * w2.x + xv.w * w3.x;
            acc[r].y += xv.x * w0.y + xv.y * w1.y + xv.z * w2.y + xv.w * w3.y;
            acc[r].z += xv.x * w0.z + xv.y * w1.z + xv.z * w2.z + xv.w * w3.z;
            acc[r].w += xv.x * w0.w + xv.y * w1.w + xv.z * w2.w + xv.w * w3.w;
        }
    }

    float4 bb = ((const float4*)b)[c4];
    const int srcLane = threadIdx.x & 16;   // 0 for lanes 0-15, 16 for 16-31

    #pragma unroll
    for (int r = 0; r < 4; r++) {
        int row = rowBase + r0 + 16 * r;
        float di = 0.0f;
        if (c4 == 0 && row < n) {
            di = rsqrtf(g_deg[row] + 1.0f);
            g_dinv[row] = di;
            g_deg[row]  = 0.0f;            // reset for next graph replay
        }
        di = __shfl_sync(0xFFFFFFFFu, di, srcLane, 32);

        if (row < n) {
            float4 xs;
            xs.x = acc[r].x * di;
            xs.y = acc[r].y * di;
            xs.z = acc[r].z * di;
            xs.w = acc[r].w * di;
            // fp16 message row (scatter source)
            __half2* hp = (__half2*)(g_xsh + (size_t)row * D);
            hp[c4 * 2 + 0] = __floats2half2_rn(xs.x, xs.y);
            hp[c4 * 2 + 1] = __floats2half2_rn(xs.z, xs.w);
            // self-loop + bias in full fp32
            float4 o;
            o.x = xs.x * di + bb.x;
            o.y = xs.y * di + bb.y;
            o.z = xs.z * di + bb.z;
            o.w = xs.w * di + bb.w;
            ((float4*)(out + (size_t)row * D))[c4] = o;
        }
    }
}

// ---------------------------------------------------------------------------
// K3: edge scatter: out[dst] += float(xsh[src]) * dinv[dst]
// 16 lanes per edge, 4 consecutive edges per thread (int4 idx loads, MLP=4).
// Per edge per lane: 8B fp16 gather (ld.nc) + 16B red.global.add.v4.f32.
// ---------------------------------------------------------------------------
__device__ __forceinline__ void red_add_v4(float* dp, float a, float b, float c, float d)
{
#if !defined(__CUDA_ARCH__) || __CUDA_ARCH__ >= 900
    asm volatile(
        "red.global.add.v4.f32 [%0], {%1, %2, %3, %4};"
        :: "l"(dp), "f"(a), "f"(b), "f"(c), "f"(d)
        : "memory");
#else
    atomicAdd(dp + 0, a);
    atomicAdd(dp + 1, b);
    atomicAdd(dp + 2, c);
    atomicAdd(dp + 3, d);
#endif
}

__device__ __forceinline__ void scatter_one(int s, int d, int lane,
                                            float* __restrict__ out)
{
    float c = g_dinv[d];
    uint2 raw = __ldg((const uint2*)(g_xsh + (size_t)s * D + lane * 4));
    float2 f0 = __half22float2(*reinterpret_cast<__half2*>(&raw.x));
    float2 f1 = __half22float2(*reinterpret_cast<__half2*>(&raw.y));
    float* dp = out + (size_t)d * D + lane * 4;
    red_add_v4(dp, f0.x * c, f0.y * c, f1.x * c, f1.y * c);
}

__global__ void __launch_bounds__(256) scatter_kernel(
    const int* __restrict__ ei, float* __restrict__ out, int E)
{
    unsigned int t = blockIdx.x * 256u + threadIdx.x;
    int g    = (int)(t >> 4);
    int lane = (int)(t & 15);
    int nquad = E >> 2;

    if (g < nquad) {
        int e = 4 * g;
        int4 ss = *(const int4*)&ei[e];
        int4 dd = *(const int4*)&ei[E + e];

        // all independent loads up front (MLP)
        float c0 = g_dinv[dd.x], c1 = g_dinv[dd.y];
        float c2 = g_dinv[dd.z], c3 = g_dinv[dd.w];
        uint2 r0 = __ldg((const uint2*)(g_xsh + (size_t)ss.x * D + lane * 4));
        uint2 r1 = __ldg((const uint2*)(g_xsh + (size_t)ss.y * D + lane * 4));
        uint2 r2 = __ldg((const uint2*)(g_xsh + (size_t)ss.z * D + lane * 4));
        uint2 r3 = __ldg((const uint2*)(g_xsh + (size_t)ss.w * D + lane * 4));

        {
            float2 a = __half22float2(*reinterpret_cast<__half2*>(&r0.x));
            float2 b = __half22float2(*reinterpret_cast<__half2*>(&r0.y));
            red_add_v4(out + (size_t)dd.x * D + lane * 4,
                       a.x * c0, a.y * c0, b.x * c0, b.y * c0);
        }
        {
            float2 a = __half22float2(*reinterpret_cast<__half2*>(&r1.x));
            float2 b = __half22float2(*reinterpret_cast<__half2*>(&r1.y));
            red_add_v4(out + (size_t)dd.y * D + lane * 4,
                       a.x * c1, a.y * c1, b.x * c1, b.y * c1);
        }
        {
            float2 a = __half22float2(*reinterpret_cast<__half2*>(&r2.x));
            float2 b = __half22float2(*reinterpret_cast<__half2*>(&r2.y));
            red_add_v4(out + (size_t)dd.z * D + lane * 4,
                       a.x * c2, a.y * c2, b.x * c2, b.y * c2);
        }
        {
            float2 a = __half22float2(*reinterpret_cast<__half2*>(&r3.x));
            float2 b = __half22float2(*reinterpret_cast<__half2*>(&r3.y));
            red_add_v4(out + (size_t)dd.w * D + lane * 4,
                       a.x * c3, a.y * c3, b.x * c3, b.y * c3);
        }
    } else if (g == nquad) {
        // tail edges (E not divisible by 4)
        for (int e = 4 * nquad; e < E; e++) {
            int s = __ldg(&ei[e]);
            int d = __ldg(&ei[E + e]);
            scatter_one(s, d, lane, out);
        }
    }
}

// ---------------------------------------------------------------------------
// Launch
// Inputs (metadata order): x [n*64] f32, edge_index [2*E] int32, W [64*64] f32,
//                          b [64] f32. Output: [n*64] f32.
// 3 launches: deg_count, gemm(+dinv+epilogue), scatter.
// ---------------------------------------------------------------------------
extern "C" void kernel_launch(void* const* d_in, const int* in_sizes, int n_in,
                              void* d_out, int out_size)
{
    const float* x  = (const float*)d_in[0];
    const int*   ei = (const int*)d_in[1];
    const float* W  = (const float*)d_in[2];
    const float* b  = (const float*)d_in[3];
    float*       out = (float*)d_out;

    const int n = in_sizes[0] / D;       // 100000
    const int E = in_sizes[1] / 2;       // 1600000

    {
        int groups = (E >> 2) + 1;
        deg_count_kernel<<<(groups + 255) / 256, 256>>>(ei + E, E);
    }
    gemm64_kernel<<<(n + 63) / 64, 256>>>(x, W, b, out, n);
    {
        int groups = (E >> 2) + 1;           // quads + tail group
        long long total = (long long)groups * 16;
        int blocks = (int)((total + 255) / 256);
        scatter_kernel<<<blocks, 256>>>(ei, out, E);
    }
}

// round 13
// speedup vs baseline: 1.1689x; 1.1689x over previous
#include <cuda_runtime.h>
#include <cuda_fp16.h>
#include <stdint.h>

#define NMAX 100000
#define EMAX 1600000
#define D 64
#define NPART 512   // >= ceil(NMAX/256) = 391

// Scratch (static device globals: allocation-free, graph-capturable).
// g_degi starts zero-initialized and is RESET in scan3 each launch, so graph
// replays are deterministic. g_fill is rewritten from the scan each launch.
__device__ __half g_xsh[(size_t)NMAX * D];  // xs = (x@W)*dinv[row], fp16
__device__ int    g_degi[NMAX];
__device__ float  g_dinv[NMAX];
__device__ int    g_rowstart[NMAX + 1];
__device__ int    g_fill[NMAX];
__device__ int    g_srclist[EMAX];
__device__ int    g_part[NPART];
__device__ int    g_blockoff[NPART];

// ---------------------------------------------------------------------------
// K1: in-degree histogram. 1 edge/thread: max cross-warp MLP on the RED path.
// ---------------------------------------------------------------------------
__global__ void deg_count_kernel(const int* __restrict__ dst, int E)
{
    int e = blockIdx.x * blockDim.x + threadIdx.x;
    if (e < E) atomicAdd(&g_degi[__ldg(&dst[e])], 1);
}

// ---------------------------------------------------------------------------
// K2a: per-block partial sums of degi (256 elements per block)
// ---------------------------------------------------------------------------
__global__ void __launch_bounds__(256) scan1_kernel(int n)
{
    __shared__ int sd[256];
    int t = threadIdx.x;
    int i = blockIdx.x * 256 + t;
    sd[t] = (i < n) ? g_degi[i] : 0;
    __syncthreads();
    #pragma unroll
    for (int ofs = 128; ofs > 0; ofs >>= 1) {
        if (t < ofs) sd[t] += sd[t + ofs];
        __syncthreads();
    }
    if (t == 0) g_part[blockIdx.x] = sd[0];
}

// ---------------------------------------------------------------------------
// K2b: single-block exclusive scan of the partials -> g_blockoff
// ---------------------------------------------------------------------------
__global__ void __launch_bounds__(512) scan2_kernel(int nblocks)
{
    __shared__ int sp[512];
    int t = threadIdx.x;
    int v0 = (t < nblocks) ? g_part[t] : 0;
    sp[t] = v0;
    __syncthreads();
    int v = v0;
    #pragma unroll
    for (int ofs = 1; ofs < 512; ofs <<= 1) {
        int u = (t >= ofs) ? sp[t - ofs] : 0;
        __syncthreads();
        v += u;
        sp[t] = v;
        __syncthreads();
    }
    if (t < nblocks) g_blockoff[t] = v - v0;   // exclusive
}

// ---------------------------------------------------------------------------
// K2c: block-local exclusive scan + offsets -> rowstart/fill; dinv; deg reset.
// ---------------------------------------------------------------------------
__global__ void __launch_bounds__(256) scan3_kernel(int n, int E)
{
    __shared__ int sd[256];
    int t = threadIdx.x;
    int i = blockIdx.x * 256 + t;
    int dg = (i < n) ? g_degi[i] : 0;
    sd[t] = dg;
    __syncthreads();
    int v = dg;
    #pragma unroll
    for (int ofs = 1; ofs < 256; ofs <<= 1) {
        int u = (t >= ofs) ? sd[t - ofs] : 0;
        __syncthreads();
        v += u;
        sd[t] = v;
        __syncthreads();
    }
    if (i < n) {
        int rs = g_blockoff[blockIdx.x] + (v - dg);  // global exclusive prefix
        g_rowstart[i] = rs;
        g_fill[i]     = rs;
        g_dinv[i]     = rsqrtf((float)(dg + 1));
        g_degi[i]     = 0;                  // reset for next graph replay
    }
    if (blockIdx.x == 0 && t == 0) g_rowstart[n] = E;
}

// ---------------------------------------------------------------------------
// K3: CSR fill: srclist[fill[dst]++] = src. 1 edge/thread.
// ---------------------------------------------------------------------------
__global__ void fill_kernel(const int* __restrict__ ei, int E)
{
    int e = blockIdx.x * blockDim.x + threadIdx.x;
    if (e < E) {
        int s = __ldg(&ei[e]);
        int d = __ldg(&ei[E + e]);
        int pos = atomicAdd(&g_fill[d], 1);
        g_srclist[pos] = s;
    }
}

// ---------------------------------------------------------------------------
// K4: xsh = fp16( (x@W) * dinv[row] )
// 256 threads, 64 rows/block, 4 rows x 4 cols register blocking,
// k-loop unrolled by 4 with LDS.128 broadcast x-row reads.
// ---------------------------------------------------------------------------
__global__ void __launch_bounds__(256) gemm64_kernel(
    const float* __restrict__ x, const float* __restrict__ W, int n)
{
    __shared__ float  sX[64][68];
    __shared__ float4 sW[64][16];

    const int t = threadIdx.x;
    const int rowBase = blockIdx.x * 64;

    {
        const float4* W4 = (const float4*)W;
        #pragma unroll
        for (int i = 0; i < 4; i++) {
            int idx = t + i * 256;
            sW[idx >> 4][idx & 15] = W4[idx];
        }
    }
    {
        #pragma unroll
        for (int i = 0; i < 4; i++) {
            int idx = t + i * 256;
            int r = idx >> 4, c4 = idx & 15;
            int row = rowBase + r;
            float4 v = make_float4(0.f, 0.f, 0.f, 0.f);
            if (row < n) v = ((const float4*)(x + (size_t)row * D))[c4];
            *(float4*)&sX[r][c4 * 4] = v;
        }
    }
    __syncthreads();

    const int c4 = t & 15;
    const int r0 = t >> 4;

    float4 acc[4];
    #pragma unroll
    for (int r = 0; r < 4; r++) acc[r] = make_float4(0.f, 0.f, 0.f, 0.f);

    #pragma unroll
    for (int k = 0; k < 64; k += 4) {
        float4 w0 = sW[k + 0][c4];
        float4 w1 = sW[k + 1][c4];
        float4 w2 = sW[k + 2][c4];
        float4 w3 = sW[k + 3][c4];
        #pragma unroll
        for (int r = 0; r < 4; r++) {
            float4 xv = *(const float4*)&sX[r0 + 16 * r][k];
            acc[r].x += xv.x * w0.x + xv.y * w1.x + xv.z * w2.x + xv.w * w3.x;
            acc[r].y += xv.x * w0.y + xv.y * w1.y + xv.z * w2.y + xv.w * w3.y;
            acc[r].z += xv.x * w0.z + xv.y * w1.z + xv.z * w2.z + xv.w * w3.z;
            acc[r].w += xv.x * w0.w + xv.y * w1.w + xv.z * w2.w + xv.w * w3.w;
        }
    }

    #pragma unroll
    for (int r = 0; r < 4; r++) {
        int row = rowBase + r0 + 16 * r;
        if (row < n) {
            float di = g_dinv[row];
            __half2* hp = (__half2*)(g_xsh + (size_t)row * D);
            hp[c4 * 2 + 0] = __floats2half2_rn(acc[r].x * di, acc[r].y * di);
            hp[c4 * 2 + 1] = __floats2half2_rn(acc[r].z * di, acc[r].w * di);
        }
    }
}

// ---------------------------------------------------------------------------
// K5: CSR gather, warp per node, MLP=8.
//   out[i] = ( xsh[i] + sum_{s in in(i)} xsh[s] ) * dinv[i] + b
// Each lane owns 2 dims (one __half2 / 4B per row load -> 128B/warp, 1 line).
// cnt is warp-uniform: all branches divergence-free.
// ---------------------------------------------------------------------------
__global__ void __launch_bounds__(256) gather_kernel(
    const float* __restrict__ b, float* __restrict__ out, int n)
{
    int warp = (int)((blockIdx.x * 256u + threadIdx.x) >> 5);
    int lane = threadIdx.x & 31;
    if (warp >= n) return;
    const int i = warp;

    const __half2* __restrict__ xbase = (const __half2*)g_xsh;

    int start = g_rowstart[i];
    int cnt   = g_rowstart[i + 1] - start;
    float di  = g_dinv[i];

    // self message (fp16 row); row stride in __half2 units = D/2 = 32
    float2 acc = __half22float2(__ldg(xbase + (size_t)i * 32 + lane));

    for (int k0 = 0; k0 < cnt; k0 += 32) {
        int m = min(cnt - k0, 32);
        int sl = (lane < m) ? __ldg(&g_srclist[start + k0 + lane]) : 0;

        int kk = 0;
        for (; kk + 8 <= m; kk += 8) {
            int s0 = __shfl_sync(0xFFFFFFFFu, sl, kk + 0);
            int s1 = __shfl_sync(0xFFFFFFFFu, sl, kk + 1);
            int s2 = __shfl_sync(0xFFFFFFFFu, sl, kk + 2);
            int s3 = __shfl_sync(0xFFFFFFFFu, sl, kk + 3);
            int s4 = __shfl_sync(0xFFFFFFFFu, sl, kk + 4);
            int s5 = __shfl_sync(0xFFFFFFFFu, sl, kk + 5);
            int s6 = __shfl_sync(0xFFFFFFFFu, sl, kk + 6);
            int s7 = __shfl_sync(0xFFFFFFFFu, sl, kk + 7);
            // 8 independent 128B row loads in flight
            __half2 v0 = __ldg(xbase + (size_t)s0 * 32 + lane);
            __half2 v1 = __ldg(xbase + (size_t)s1 * 32 + lane);
            __half2 v2 = __ldg(xbase + (size_t)s2 * 32 + lane);
            __half2 v3 = __ldg(xbase + (size_t)s3 * 32 + lane);
            __half2 v4 = __ldg(xbase + (size_t)s4 * 32 + lane);
            __half2 v5 = __ldg(xbase + (size_t)s5 * 32 + lane);
            __half2 v6 = __ldg(xbase + (size_t)s6 * 32 + lane);
            __half2 v7 = __ldg(xbase + (size_t)s7 * 32 + lane);
            float2 f;
            f = __half22float2(v0); acc.x += f.x; acc.y += f.y;
            f = __half22float2(v1); acc.x += f.x; acc.y += f.y;
            f = __half22float2(v2); acc.x += f.x; acc.y += f.y;
            f = __half22float2(v3); acc.x += f.x; acc.y += f.y;
            f = __half22float2(v4); acc.x += f.x; acc.y += f.y;
            f = __half22float2(v5); acc.x += f.x; acc.y += f.y;
            f = __half22float2(v6); acc.x += f.x; acc.y += f.y;
            f = __half22float2(v7); acc.x += f.x; acc.y += f.y;
        }
        for (; kk < m; kk++) {
            int s = __shfl_sync(0xFFFFFFFFu, sl, kk);
            float2 f = __half22float2(__ldg(xbase + (size_t)s * 32 + lane));
            acc.x += f.x; acc.y += f.y;
        }
    }

    float2 bb = *((const float2*)b + lane);
    float2 o;
    o.x = acc.x * di + bb.x;
    o.y = acc.y * di + bb.y;
    *((float2*)(out + (size_t)i * D) + lane) = o;
}

// ---------------------------------------------------------------------------
// Launch
// Inputs (metadata order): x [n*64] f32, edge_index [2*E] int32, W [64*64] f32,
//                          b [64] f32. Output: [n*64] f32.
// 7 launches: deg, scan1, scan2, scan3, fill, gemm, gather.
// ---------------------------------------------------------------------------
extern "C" void kernel_launch(void* const* d_in, const int* in_sizes, int n_in,
                              void* d_out, int out_size)
{
    const float* x  = (const float*)d_in[0];
    const int*   ei = (const int*)d_in[1];
    const float* W  = (const float*)d_in[2];
    const float* b  = (const float*)d_in[3];
    float*       out = (float*)d_out;

    const int n = in_sizes[0] / D;       // 100000
    const int E = in_sizes[1] / 2;       // 1600000
    const int nblocks = (n + 255) / 256; // 391

    deg_count_kernel<<<(E + 255) / 256, 256>>>(ei + E, E);
    scan1_kernel<<<nblocks, 256>>>(n);
    scan2_kernel<<<1, 512>>>(nblocks);
    scan3_kernel<<<nblocks, 256>>>(n, E);
    fill_kernel<<<(E + 255) / 256, 256>>>(ei, E);
    gemm64_kernel<<<(n + 63) / 64, 256>>>(x, W, n);
    {
        int total = n * 32;                      // 1 warp per node
        gather_kernel<<<(total + 255) / 256, 256>>>(b, out, n);
    }
}